// round 1
// baseline (speedup 1.0000x reference)
#include <cuda_runtime.h>
#include <math.h>

#define CC 256
#define NN 4096
#define BB 16
#define NH 8
#define HD 32
#define HH 64
#define WW 64
#define M_QKV 768

// ---------------- scratch (device globals; no allocation allowed) ----------------
__device__ float g_qkv[(size_t)BB * M_QKV * NN];   // (B, 768, N): q rows 0..255, k 256..511, v 512..767
__device__ float g_mid[(size_t)BB * CC * NN];      // (B, C, N) pre-projection output
__device__ float g_kvs[BB * NH * HD * HD];         // per-head kv_state
__device__ float g_ksum[BB * NH * HD];             // per-head k column sums
__device__ float g_Wcat[M_QKV * CC];               // [Wq; Wkv]
__device__ float g_bcat[M_QKV];                    // [bq; bkv]
__device__ float g_invscale[CC];                   // 1/softplus(scale_param)

// ---------------- prep: concat weights + compute inv softplus scale ----------------
__global__ void prep_kernel(const float* __restrict__ Wq, const float* __restrict__ bq,
                            const float* __restrict__ Wkv, const float* __restrict__ bkv,
                            const float* __restrict__ scale_param) {
    int r = blockIdx.x;
    int t = threadIdx.x;
    const float* src = (r < CC) ? (Wq + (size_t)r * CC) : (Wkv + (size_t)(r - CC) * CC);
    g_Wcat[(size_t)r * CC + t] = src[t];
    if (t == 0) {
        g_bcat[r] = (r < CC) ? bq[r] : bkv[r - CC];
        if (r < CC) {
            float s = scale_param[r];
            float sp = (s > 20.f) ? s : log1pf(expf(s));
            g_invscale[r] = 1.0f / sp;
        }
    }
}

// ---------------- generic fp32 tiled GEMM: Y[b] = A(MxK) @ X[b](KxN) + bias ----------------
#define GBM 64
#define GBN 128
#define GBK 16

__global__ __launch_bounds__(256)
void gemm_bias_kernel(const float* __restrict__ A, const float* __restrict__ bias,
                      const float* __restrict__ X, float* __restrict__ Y,
                      int M, int K, int N) {
    __shared__ float As[GBK][GBM + 4];
    __shared__ float Bs[GBK][GBN];
    int tid = threadIdx.x;
    int n0 = blockIdx.x * GBN;
    int m0 = blockIdx.y * GBM;
    const float* Xb = X + (size_t)blockIdx.z * K * N;
    float*       Yb = Y + (size_t)blockIdx.z * M * N;

    float acc[4][8];
#pragma unroll
    for (int i = 0; i < 4; i++)
#pragma unroll
        for (int j = 0; j < 8; j++) acc[i][j] = 0.f;

    int a_row = tid >> 2;          // 0..63
    int a_col = (tid & 3) * 4;     // 0,4,8,12
    int b_row = tid >> 5;          // 0..7
    int b_col = (tid & 31) * 4;    // 0..124
    int tm = (tid >> 4) * 4;       // 0..60
    int tn = (tid & 15) * 8;       // 0..120

    for (int k0 = 0; k0 < K; k0 += GBK) {
        float4 av = *(const float4*)(A + (size_t)(m0 + a_row) * K + k0 + a_col);
        As[a_col + 0][a_row] = av.x;
        As[a_col + 1][a_row] = av.y;
        As[a_col + 2][a_row] = av.z;
        As[a_col + 3][a_row] = av.w;
#pragma unroll
        for (int r = 0; r < 2; r++) {
            int kr = b_row + r * 8;
            float4 bv = *(const float4*)(Xb + (size_t)(k0 + kr) * N + n0 + b_col);
            *(float4*)&Bs[kr][b_col] = bv;
        }
        __syncthreads();
#pragma unroll
        for (int k = 0; k < GBK; k++) {
            float ar[4], br[8];
#pragma unroll
            for (int i = 0; i < 4; i++) ar[i] = As[k][tm + i];
#pragma unroll
            for (int j = 0; j < 8; j++) br[j] = Bs[k][tn + j];
#pragma unroll
            for (int i = 0; i < 4; i++)
#pragma unroll
                for (int j = 0; j < 8; j++) acc[i][j] += ar[i] * br[j];
        }
        __syncthreads();
    }
#pragma unroll
    for (int i = 0; i < 4; i++) {
        float bv = bias[m0 + tm + i];
#pragma unroll
        for (int j = 0; j < 8; j++)
            Yb[(size_t)(m0 + tm + i) * N + n0 + tn + j] = acc[i][j] + bv;
    }
}

// ---------------- focusing transform on q and k (rows 0..511 of qkv) ----------------
__global__ __launch_bounds__(256)
void focus_kernel() {
    __shared__ float sinv[CC];
    int tid = threadIdx.x;
    sinv[tid] = g_invscale[tid];
    __syncthreads();
    int b = blockIdx.y;
    int n = blockIdx.x * 256 + tid;
#pragma unroll
    for (int part = 0; part < 2; part++) {
        float* base = g_qkv + ((size_t)b * M_QKV + part * CC) * NN + n;
        float s2 = 0.f, s6 = 0.f;
        for (int c = 0; c < CC; c++) {
            float v = base[(size_t)c * NN];
            v = fmaxf(v, 0.f) + 1e-6f;
            v *= sinv[c];
            float v2 = v * v;
            float v3 = v2 * v;
            s2 += v2;
            s6 += v3 * v3;
        }
        float f = sqrtf(s2 / s6);   // ||q|| / ||q^3||
        for (int c = 0; c < CC; c++) {
            float v = base[(size_t)c * NN];
            v = fmaxf(v, 0.f) + 1e-6f;
            v *= sinv[c];
            base[(size_t)c * NN] = v * v * v * f;
        }
    }
}

// ---------------- per-head kv_state (32x32) + ksum ----------------
#define CHUNK 128
__global__ __launch_bounds__(256)
void kvstate_kernel() {
    int bh = blockIdx.x;            // 0..127
    int b = bh >> 3, h = bh & 7;
    const float* kbase = g_qkv + ((size_t)b * M_QKV + CC + h * HD) * NN;
    const float* vbase = g_qkv + ((size_t)b * M_QKV + 2 * CC + h * HD) * NN;
    __shared__ float sk[HD][CHUNK + 1];
    __shared__ float sv[HD][CHUNK + 1];
    int tid = threadIdx.x;
    int c  = tid >> 3;              // 0..31
    int d4 = (tid & 7) * 4;         // 0..28
    int lrow = tid >> 3;
    int lcol = (tid & 7) * 16;
    float acc[4] = {0, 0, 0, 0};
    float ks = 0.f;

    for (int j0 = 0; j0 < NN; j0 += CHUNK) {
#pragma unroll
        for (int i = 0; i < 16; i += 4) {
            float4 k4 = *(const float4*)(kbase + (size_t)lrow * NN + j0 + lcol + i);
            sk[lrow][lcol + i + 0] = k4.x;
            sk[lrow][lcol + i + 1] = k4.y;
            sk[lrow][lcol + i + 2] = k4.z;
            sk[lrow][lcol + i + 3] = k4.w;
            float4 v4 = *(const float4*)(vbase + (size_t)lrow * NN + j0 + lcol + i);
            sv[lrow][lcol + i + 0] = v4.x;
            sv[lrow][lcol + i + 1] = v4.y;
            sv[lrow][lcol + i + 2] = v4.z;
            sv[lrow][lcol + i + 3] = v4.w;
        }
        __syncthreads();
        for (int j = 0; j < CHUNK; j++) {
            float kc = sk[c][j];
            ks += kc;
#pragma unroll
            for (int i = 0; i < 4; i++) acc[i] += kc * sv[d4 + i][j];
        }
        __syncthreads();
    }
    float* kvs = g_kvs + (size_t)bh * HD * HD;
#pragma unroll
    for (int i = 0; i < 4; i++) kvs[c * HD + d4 + i] = acc[i];
    if ((tid & 7) == 0) g_ksum[bh * HD + c] = ks;
}

// ---------------- depthwise 5x5 conv on v -> writes g_mid ----------------
__global__ __launch_bounds__(256)
void dwconv_kernel(const float* __restrict__ dwc_w, const float* __restrict__ dwc_b) {
    int bh = blockIdx.y;
    int b = bh >> 3, h = bh & 7;
    int ty0 = (blockIdx.x >> 2) * 16;
    int tx0 = (blockIdx.x & 3) * 16;
    int tid = threadIdx.x;
    int lx = tid & 15, ly = tid >> 4;
    __shared__ float tile[20][21];
    __shared__ float wloc[25];
    int gy = ty0 + ly, gx = tx0 + lx;
    for (int d = 0; d < HD; d++) {
        const float* vrow = g_qkv + ((size_t)b * M_QKV + 2 * CC + h * HD + d) * NN;
        if (tid < 25) wloc[tid] = dwc_w[d * 25 + tid];
        for (int i = tid; i < 20 * 20; i += 256) {
            int ry = i / 20, rx = i % 20;
            int sy = ty0 - 2 + ry, sx = tx0 - 2 + rx;
            float v = 0.f;
            if (sy >= 0 && sy < HH && sx >= 0 && sx < WW) v = vrow[sy * WW + sx];
            tile[ry][rx] = v;
        }
        __syncthreads();
        float accv = dwc_b[d];
#pragma unroll
        for (int ky = 0; ky < 5; ky++)
#pragma unroll
            for (int kx = 0; kx < 5; kx++)
                accv += tile[ly + ky][lx + kx] * wloc[ky * 5 + kx];
        g_mid[((size_t)b * CC + h * HD + d) * NN + gy * WW + gx] = accv;
        __syncthreads();
    }
}

// ---------------- attention output: g_mid += z * (kv_state^T q) ----------------
__global__ __launch_bounds__(256)
void attn_out_kernel() {
    int bh = blockIdx.y;
    int b = bh >> 3, h = bh & 7;
    int tid = threadIdx.x;
    int n = blockIdx.x * 256 + tid;
    __shared__ float skvs[HD * HD];
    __shared__ float sks[HD];
    for (int i = tid; i < HD * HD; i += 256) skvs[i] = g_kvs[(size_t)bh * HD * HD + i];
    if (tid < HD) sks[tid] = g_ksum[bh * HD + tid];
    __syncthreads();

    const float* qbase = g_qkv + ((size_t)b * M_QKV + h * HD) * NN + n;
    float acc[HD];
#pragma unroll
    for (int d = 0; d < HD; d++) acc[d] = 0.f;
    float zacc = 0.f;
#pragma unroll
    for (int c = 0; c < HD; c++) {
        float qv = qbase[(size_t)c * NN];
        zacc += qv * sks[c];
#pragma unroll
        for (int d = 0; d < HD; d++) acc[d] += qv * skvs[c * HD + d];
    }
    float z = 1.0f / (zacc + 1e-6f);
    float* obase = g_mid + ((size_t)b * CC + h * HD) * NN + n;
#pragma unroll
    for (int d = 0; d < HD; d++) obase[(size_t)d * NN] += acc[d] * z;
}

// ---------------- launch ----------------
extern "C" void kernel_launch(void* const* d_in, const int* in_sizes, int n_in,
                              void* d_out, int out_size) {
    const float* x           = (const float*)d_in[0];
    const float* Wq          = (const float*)d_in[1];
    const float* bq          = (const float*)d_in[2];
    const float* Wkv         = (const float*)d_in[3];
    const float* bkv         = (const float*)d_in[4];
    const float* Wproj       = (const float*)d_in[5];
    const float* bproj       = (const float*)d_in[6];
    const float* dwc_w       = (const float*)d_in[7];
    const float* dwc_b       = (const float*)d_in[8];
    const float* scale_param = (const float*)d_in[9];
    float* out = (float*)d_out;

    // device-symbol addresses (host-side queries; no allocation, capture-safe)
    float *p_qkv, *p_mid, *p_Wcat, *p_bcat;
    cudaGetSymbolAddress((void**)&p_qkv,  g_qkv);
    cudaGetSymbolAddress((void**)&p_mid,  g_mid);
    cudaGetSymbolAddress((void**)&p_Wcat, g_Wcat);
    cudaGetSymbolAddress((void**)&p_bcat, g_bcat);

    prep_kernel<<<M_QKV, CC>>>(Wq, bq, Wkv, bkv, scale_param);

    // QKV projection: (768x256) @ (256x4096) per batch
    {
        dim3 grid(NN / GBN, M_QKV / GBM, BB);
        gemm_bias_kernel<<<grid, 256>>>(p_Wcat, p_bcat, x, p_qkv, M_QKV, CC, NN);
    }

    // focusing transform on q, k
    {
        dim3 grid(NN / 256, BB);
        focus_kernel<<<grid, 256>>>();
    }

    // per-head kv_state + ksum
    kvstate_kernel<<<BB * NH, 256>>>();

    // depthwise conv (writes g_mid)
    {
        dim3 grid(16, BB * NH);
        dwconv_kernel<<<grid, 256>>>(dwc_w, dwc_b);
    }

    // attention output (+= into g_mid)
    {
        dim3 grid(NN / 256, BB * NH);
        attn_out_kernel<<<grid, 256>>>();
    }

    // output projection: (256x256) @ (256x4096) per batch -> d_out (B,C,H,W)
    {
        dim3 grid(NN / GBN, CC / GBM, BB);
        gemm_bias_kernel<<<grid, 256>>>(Wproj, bproj, p_mid, out, CC, CC, NN);
    }
}

// round 3
// speedup vs baseline: 1.9449x; 1.9449x over previous
#include <cuda_runtime.h>
#include <cuda_bf16.h>
#include <math.h>
#include <stdint.h>

#define CC 256
#define NN 4096
#define BB 16
#define NH 8
#define HD 32
#define HH 64
#define WW 64
#define M_QKV 768
#define SEGS 8

// ---------------- scratch (device globals; no allocation allowed) ----------------
__device__ float g_qkv[(size_t)BB * M_QKV * NN];   // (B, 768, N) fp32
__device__ float g_mid[(size_t)BB * CC * NN];      // (B, C, N) dwconv output fp32
__device__ float g_kvp[SEGS * BB * NH * HD * HD];  // partial kv states
__device__ float g_ksp[SEGS * BB * NH * HD];       // partial ksums
__device__ float g_bcat[M_QKV];
__device__ float g_invscale[CC];
// bf16 hi/lo buffers (uint4-typed for 16B alignment)
__device__ uint4 g_whi4 [M_QKV * CC * 2 / 16];
__device__ uint4 g_wlo4 [M_QKV * CC * 2 / 16];
__device__ uint4 g_pwhi4[CC * CC * 2 / 16];
__device__ uint4 g_pwlo4[CC * CC * 2 / 16];
__device__ uint4 g_xhi4 [(size_t)BB * CC * NN * 2 / 16];
__device__ uint4 g_xlo4 [(size_t)BB * CC * NN * 2 / 16];
__device__ uint4 g_mhi4 [(size_t)BB * CC * NN * 2 / 16];
__device__ uint4 g_mlo4 [(size_t)BB * CC * NN * 2 / 16];

// ---------------- ptx helpers (baseline sm_80+ ISA only; no 'a' features) ----------------
__device__ __forceinline__ uint32_t smem_u32(const void* p) {
    uint32_t a;
    asm("{ .reg .u64 t; cvta.to.shared.u64 t, %1; cvt.u32.u64 %0, t; }" : "=r"(a) : "l"(p));
    return a;
}
__device__ __forceinline__ void cp_async16(uint32_t saddr, const void* gptr) {
    asm volatile("cp.async.cg.shared.global [%0], [%1], 16;"
                 :: "r"(saddr), "l"(__cvta_generic_to_global(gptr)) : "memory");
}
__device__ __forceinline__ void ldsm_x4(uint32_t* r, uint32_t addr) {
    asm volatile("ldmatrix.sync.aligned.m8n8.x4.shared.b16 {%0,%1,%2,%3}, [%4];"
                 : "=r"(r[0]), "=r"(r[1]), "=r"(r[2]), "=r"(r[3]) : "r"(addr));
}
__device__ __forceinline__ void ldsm_x4_t(uint32_t* r, uint32_t addr) {
    asm volatile("ldmatrix.sync.aligned.m8n8.x4.trans.shared.b16 {%0,%1,%2,%3}, [%4];"
                 : "=r"(r[0]), "=r"(r[1]), "=r"(r[2]), "=r"(r[3]) : "r"(addr));
}
__device__ __forceinline__ void mma_bf16(float* c, const uint32_t* a, const uint32_t* b) {
    asm volatile(
        "mma.sync.aligned.m16n8k16.row.col.f32.bf16.bf16.f32 "
        "{%0,%1,%2,%3}, {%4,%5,%6,%7}, {%8,%9}, {%0,%1,%2,%3};"
        : "+f"(c[0]), "+f"(c[1]), "+f"(c[2]), "+f"(c[3])
        : "r"(a[0]), "r"(a[1]), "r"(a[2]), "r"(a[3]), "r"(b[0]), "r"(b[1]));
}

// ---------------- prep: weight hi/lo split + biases + inv softplus scale ----------------
__global__ void prep_kernel(const float* __restrict__ Wq, const float* __restrict__ bq,
                            const float* __restrict__ Wkv, const float* __restrict__ bkv,
                            const float* __restrict__ Wproj, const float* __restrict__ scale_param) {
    int r = blockIdx.x, t = threadIdx.x;
    float w = (r < CC) ? Wq[(size_t)r * CC + t] : Wkv[(size_t)(r - CC) * CC + t];
    __nv_bfloat16 h = __float2bfloat16(w);
    ((__nv_bfloat16*)g_whi4)[(size_t)r * CC + t] = h;
    ((__nv_bfloat16*)g_wlo4)[(size_t)r * CC + t] = __float2bfloat16(w - __bfloat162float(h));
    if (r < CC) {
        float pw = Wproj[(size_t)r * CC + t];
        __nv_bfloat16 ph = __float2bfloat16(pw);
        ((__nv_bfloat16*)g_pwhi4)[r * CC + t] = ph;
        ((__nv_bfloat16*)g_pwlo4)[r * CC + t] = __float2bfloat16(pw - __bfloat162float(ph));
    }
    if (t == 0) {
        g_bcat[r] = (r < CC) ? bq[r] : bkv[r - CC];
        if (r < CC) {
            float s = scale_param[r];
            float sp = (s > 20.f) ? s : log1pf(expf(s));
            g_invscale[r] = 1.0f / sp;
        }
    }
}

// ---------------- split fp32 into bf16 hi/lo ----------------
__global__ __launch_bounds__(256)
void split_kernel(const float4* __restrict__ src, __nv_bfloat16* __restrict__ hi,
                  __nv_bfloat16* __restrict__ lo, int n4) {
    int i = blockIdx.x * 256 + threadIdx.x;
    if (i >= n4) return;
    float4 v = src[i];
    __nv_bfloat16 h0 = __float2bfloat16(v.x), h1 = __float2bfloat16(v.y);
    __nv_bfloat16 h2 = __float2bfloat16(v.z), h3 = __float2bfloat16(v.w);
    __nv_bfloat16 l0 = __float2bfloat16(v.x - __bfloat162float(h0));
    __nv_bfloat16 l1 = __float2bfloat16(v.y - __bfloat162float(h1));
    __nv_bfloat16 l2 = __float2bfloat16(v.z - __bfloat162float(h2));
    __nv_bfloat16 l3 = __float2bfloat16(v.w - __bfloat162float(h3));
    __nv_bfloat162* hp = (__nv_bfloat162*)(hi + 4 * (size_t)i);
    __nv_bfloat162* lp = (__nv_bfloat162*)(lo + 4 * (size_t)i);
    hp[0] = __halves2bfloat162(h0, h1);
    hp[1] = __halves2bfloat162(h2, h3);
    lp[0] = __halves2bfloat162(l0, l1);
    lp[1] = __halves2bfloat162(l2, l3);
}

// ---------------- mma.sync GEMM: out[b] = A(Mx256) @ B[b](256x4096) + bias ----------------
// 3-term bf16 hi/lo split as virtual K = 768. CTA tile 128x128, 8 warps of 32x64.
// cp.async 4-stage pipeline; ldmatrix with padded rows (A 80B, B 272B) for bank-free access.
#define STAGES 4
#define A_STRIDE 80
#define B_STRIDE 272
#define A_BYTES (128 * A_STRIDE)          // 10240
#define B_TILE_BYTES (32 * B_STRIDE)      // 8704
#define STAGE_BYTES (A_BYTES + B_TILE_BYTES)
#define NCHUNKS 24

__global__ __launch_bounds__(256)
void gemm_mma_kernel(const __nv_bfloat16* __restrict__ Ahi, const __nv_bfloat16* __restrict__ Alo,
                     const __nv_bfloat16* __restrict__ Bhi, const __nv_bfloat16* __restrict__ Blo,
                     const float* __restrict__ bias, float* __restrict__ out, int M) {
    extern __shared__ char smem[];
    uint32_t sb = smem_u32(smem);
    int tid = threadIdx.x, lane = tid & 31, wid = tid >> 5;
    int n0 = blockIdx.x * 128;
    int mbase = blockIdx.y * 128;
    int bz = blockIdx.z;
    int wm = (wid & 3) * 32;       // warp m offset in CTA tile
    int wn = (wid >> 2) * 64;      // warp n offset in CTA tile

    const __nv_bfloat16* Bhi_b = Bhi + (size_t)bz * CC * NN;
    const __nv_bfloat16* Blo_b = Blo + (size_t)bz * CC * NN;

    float acc[2][8][4];
#pragma unroll
    for (int mt = 0; mt < 2; mt++)
#pragma unroll
        for (int nt = 0; nt < 8; nt++)
#pragma unroll
            for (int i = 0; i < 4; i++) acc[mt][nt][i] = 0.f;

    // thread load mapping (constant across chunks)
    int a_row0 = (tid * 2) >> 2, a_kc0 = (tid * 2) & 3;
    int a_row1 = (tid * 2 + 1) >> 2, a_kc1 = (tid * 2 + 1) & 3;
    int b_row0 = (tid * 2) >> 4, b_nc0 = (tid * 2) & 15;
    int b_row1 = (tid * 2 + 1) >> 4, b_nc1 = (tid * 2 + 1) & 15;

    auto issue_load = [&](int ck) {
        if (ck < NCHUNKS) {
            int term = ck >> 3;            // 0,1,2
            int kb = (ck & 7) * 32;        // k base within 256
            const __nv_bfloat16* As = (term == 2) ? Alo : Ahi;
            const __nv_bfloat16* Bs = (term == 1) ? Blo_b : Bhi_b;
            int s = ck & (STAGES - 1);
            uint32_t sA = sb + s * STAGE_BYTES;
            uint32_t sB = sA + A_BYTES;
            cp_async16(sA + a_row0 * A_STRIDE + a_kc0 * 16,
                       As + (size_t)(mbase + a_row0) * CC + kb + a_kc0 * 8);
            cp_async16(sA + a_row1 * A_STRIDE + a_kc1 * 16,
                       As + (size_t)(mbase + a_row1) * CC + kb + a_kc1 * 8);
            cp_async16(sB + b_row0 * B_STRIDE + b_nc0 * 16,
                       Bs + (size_t)(kb + b_row0) * NN + n0 + b_nc0 * 8);
            cp_async16(sB + b_row1 * B_STRIDE + b_nc1 * 16,
                       Bs + (size_t)(kb + b_row1) * NN + n0 + b_nc1 * 8);
        }
        asm volatile("cp.async.commit_group;" ::: "memory");
    };

    issue_load(0);
    issue_load(1);
    issue_load(2);

    int li = lane >> 3, lr = lane & 7;   // ldmatrix lane decomposition

    for (int ck = 0; ck < NCHUNKS; ck++) {
        asm volatile("cp.async.wait_group 2;" ::: "memory");
        __syncthreads();
        issue_load(ck + 3);

        int s = ck & (STAGES - 1);
        uint32_t sA = sb + s * STAGE_BYTES;
        uint32_t sB = sA + A_BYTES;
#pragma unroll
        for (int ks = 0; ks < 2; ks++) {
            uint32_t af[2][4];
#pragma unroll
            for (int mt = 0; mt < 2; mt++) {
                uint32_t addr = sA + (uint32_t)(wm + mt * 16 + (li & 1) * 8 + lr) * A_STRIDE
                                   + (uint32_t)(ks * 32 + (li >> 1) * 16);
                ldsm_x4(af[mt], addr);
            }
            uint32_t bf[8][2];
#pragma unroll
            for (int j = 0; j < 4; j++) {
                uint32_t addr = sB + (uint32_t)(ks * 16 + (li & 1) * 8 + lr) * B_STRIDE
                                   + (uint32_t)(wn + j * 16 + (li >> 1) * 8) * 2;
                uint32_t t4[4];
                ldsm_x4_t(t4, addr);
                bf[2 * j][0] = t4[0]; bf[2 * j][1] = t4[1];
                bf[2 * j + 1][0] = t4[2]; bf[2 * j + 1][1] = t4[3];
            }
#pragma unroll
            for (int mt = 0; mt < 2; mt++)
#pragma unroll
                for (int nt = 0; nt < 8; nt++)
                    mma_bf16(acc[mt][nt], af[mt], bf[nt]);
        }
        __syncthreads();
    }

    // epilogue
    int g = lane >> 2, tg = lane & 3;
#pragma unroll
    for (int mt = 0; mt < 2; mt++) {
        int m = mbase + wm + mt * 16 + g;
        float bv0 = bias[m], bv1 = bias[m + 8];
        float* po0 = out + (size_t)(bz * M + m) * NN + n0 + wn + tg * 2;
        float* po1 = po0 + 8 * (size_t)NN;
#pragma unroll
        for (int nt = 0; nt < 8; nt++) {
            float2 w0 = make_float2(acc[mt][nt][0] + bv0, acc[mt][nt][1] + bv0);
            float2 w1 = make_float2(acc[mt][nt][2] + bv1, acc[mt][nt][3] + bv1);
            *(float2*)(po0 + nt * 8) = w0;
            *(float2*)(po1 + nt * 8) = w1;
        }
    }
}

// ---------------- focusing transform on q and k ----------------
__global__ __launch_bounds__(256)
void focus_kernel() {
    __shared__ float sinv[CC];
    int tid = threadIdx.x;
    sinv[tid] = g_invscale[tid];
    __syncthreads();
    int b = blockIdx.y;
    int n = blockIdx.x * 256 + tid;
#pragma unroll
    for (int part = 0; part < 2; part++) {
        float* base = g_qkv + ((size_t)b * M_QKV + part * CC) * NN + n;
        float s2 = 0.f, s6 = 0.f;
        for (int c = 0; c < CC; c++) {
            float v = base[(size_t)c * NN];
            v = fmaxf(v, 0.f) + 1e-6f;
            v *= sinv[c];
            float v2 = v * v;
            float v3 = v2 * v;
            s2 += v2;
            s6 += v3 * v3;
        }
        float f = sqrtf(s2 / s6);
        for (int c = 0; c < CC; c++) {
            float v = base[(size_t)c * NN];
            v = fmaxf(v, 0.f) + 1e-6f;
            v *= sinv[c];
            base[(size_t)c * NN] = v * v * v * f;
        }
    }
}

// ---------------- per-head kv_state partials (split over N segments) ----------------
#define CHUNK 128
__global__ __launch_bounds__(256)
void kvstate_kernel() {
    int bh = blockIdx.x, seg = blockIdx.y;
    int b = bh >> 3, h = bh & 7;
    const float* kbase = g_qkv + ((size_t)b * M_QKV + CC + h * HD) * NN;
    const float* vbase = g_qkv + ((size_t)b * M_QKV + 2 * CC + h * HD) * NN;
    __shared__ float sk[HD][CHUNK + 1];
    __shared__ float sv[HD][CHUNK + 1];
    int tid = threadIdx.x;
    int c = tid >> 3, d4 = (tid & 7) * 4;
    int lrow = tid >> 3, lcol = (tid & 7) * 16;
    float acc[4] = {0, 0, 0, 0};
    float ks = 0.f;
    int j_begin = seg * (NN / SEGS);

    for (int j0 = j_begin; j0 < j_begin + NN / SEGS; j0 += CHUNK) {
#pragma unroll
        for (int i = 0; i < 16; i += 4) {
            float4 k4 = *(const float4*)(kbase + (size_t)lrow * NN + j0 + lcol + i);
            sk[lrow][lcol + i + 0] = k4.x; sk[lrow][lcol + i + 1] = k4.y;
            sk[lrow][lcol + i + 2] = k4.z; sk[lrow][lcol + i + 3] = k4.w;
            float4 v4 = *(const float4*)(vbase + (size_t)lrow * NN + j0 + lcol + i);
            sv[lrow][lcol + i + 0] = v4.x; sv[lrow][lcol + i + 1] = v4.y;
            sv[lrow][lcol + i + 2] = v4.z; sv[lrow][lcol + i + 3] = v4.w;
        }
        __syncthreads();
        for (int j = 0; j < CHUNK; j++) {
            float kc = sk[c][j];
            ks += kc;
#pragma unroll
            for (int i = 0; i < 4; i++) acc[i] += kc * sv[d4 + i][j];
        }
        __syncthreads();
    }
    float* kvs = g_kvp + ((size_t)seg * BB * NH + bh) * HD * HD;
#pragma unroll
    for (int i = 0; i < 4; i++) kvs[c * HD + d4 + i] = acc[i];
    if ((tid & 7) == 0) g_ksp[((size_t)seg * BB * NH + bh) * HD + c] = ks;
}

// ---------------- depthwise 5x5 conv on v -> writes g_mid (fp32) ----------------
__global__ __launch_bounds__(256)
void dwconv_kernel(const float* __restrict__ dwc_w, const float* __restrict__ dwc_b) {
    int bh = blockIdx.y;
    int b = bh >> 3, h = bh & 7;
    int ty0 = (blockIdx.x >> 2) * 16;
    int tx0 = (blockIdx.x & 3) * 16;
    int tid = threadIdx.x;
    int lx = tid & 15, ly = tid >> 4;
    __shared__ float tile[20][21];
    __shared__ float wloc[25];
    int gy = ty0 + ly, gx = tx0 + lx;
    for (int d = 0; d < HD; d++) {
        const float* vrow = g_qkv + ((size_t)b * M_QKV + 2 * CC + h * HD + d) * NN;
        if (tid < 25) wloc[tid] = dwc_w[d * 25 + tid];
        for (int i = tid; i < 20 * 20; i += 256) {
            int ry = i / 20, rx = i % 20;
            int sy = ty0 - 2 + ry, sx = tx0 - 2 + rx;
            float v = 0.f;
            if (sy >= 0 && sy < HH && sx >= 0 && sx < WW) v = vrow[sy * WW + sx];
            tile[ry][rx] = v;
        }
        __syncthreads();
        float accv = dwc_b[d];
#pragma unroll
        for (int ky = 0; ky < 5; ky++)
#pragma unroll
            for (int kx = 0; kx < 5; kx++)
                accv += tile[ly + ky][lx + kx] * wloc[ky * 5 + kx];
        g_mid[((size_t)b * CC + h * HD + d) * NN + gy * WW + gx] = accv;
        __syncthreads();
    }
}

// ---------------- attention output: mid + z*(kvs^T q) -> bf16 hi/lo ----------------
__global__ __launch_bounds__(256)
void attn_out_kernel() {
    int bh = blockIdx.y;
    int b = bh >> 3, h = bh & 7;
    int tid = threadIdx.x;
    int n = blockIdx.x * 256 + tid;
    __shared__ float skvs[HD * HD];
    __shared__ float sks[HD];
    for (int i = tid; i < HD * HD; i += 256) {
        float s = 0.f;
#pragma unroll
        for (int seg = 0; seg < SEGS; seg++)
            s += g_kvp[((size_t)seg * BB * NH + bh) * HD * HD + i];
        skvs[i] = s;
    }
    if (tid < HD) {
        float s = 0.f;
#pragma unroll
        for (int seg = 0; seg < SEGS; seg++)
            s += g_ksp[((size_t)seg * BB * NH + bh) * HD + tid];
        sks[tid] = s;
    }
    __syncthreads();

    const float* qbase = g_qkv + ((size_t)b * M_QKV + h * HD) * NN + n;
    float acc[HD];
#pragma unroll
    for (int d = 0; d < HD; d++) acc[d] = 0.f;
    float zacc = 0.f;
#pragma unroll
    for (int c = 0; c < HD; c++) {
        float qv = qbase[(size_t)c * NN];
        zacc += qv * sks[c];
#pragma unroll
        for (int d = 0; d < HD; d++) acc[d] += qv * skvs[c * HD + d];
    }
    float z = 1.0f / (zacc + 1e-6f);
    __nv_bfloat16* mh = (__nv_bfloat16*)g_mhi4;
    __nv_bfloat16* ml = (__nv_bfloat16*)g_mlo4;
#pragma unroll
    for (int d = 0; d < HD; d++) {
        size_t off = ((size_t)b * CC + h * HD + d) * NN + n;
        float v = g_mid[off] + acc[d] * z;
        __nv_bfloat16 hh = __float2bfloat16(v);
        mh[off] = hh;
        ml[off] = __float2bfloat16(v - __bfloat162float(hh));
    }
}

// ---------------- launch ----------------
extern "C" void kernel_launch(void* const* d_in, const int* in_sizes, int n_in,
                              void* d_out, int out_size) {
    const float* x           = (const float*)d_in[0];
    const float* Wq          = (const float*)d_in[1];
    const float* bq          = (const float*)d_in[2];
    const float* Wkv         = (const float*)d_in[3];
    const float* bkv         = (const float*)d_in[4];
    const float* Wproj       = (const float*)d_in[5];
    const float* bproj       = (const float*)d_in[6];
    const float* dwc_w       = (const float*)d_in[7];
    const float* dwc_b       = (const float*)d_in[8];
    const float* scale_param = (const float*)d_in[9];
    float* out = (float*)d_out;

    float *p_qkv, *p_bcat;
    uint4 *p_whi, *p_wlo, *p_pwhi, *p_pwlo, *p_xhi, *p_xlo, *p_mhi, *p_mlo;
    cudaGetSymbolAddress((void**)&p_qkv,  g_qkv);
    cudaGetSymbolAddress((void**)&p_bcat, g_bcat);
    cudaGetSymbolAddress((void**)&p_whi,  g_whi4);
    cudaGetSymbolAddress((void**)&p_wlo,  g_wlo4);
    cudaGetSymbolAddress((void**)&p_pwhi, g_pwhi4);
    cudaGetSymbolAddress((void**)&p_pwlo, g_pwlo4);
    cudaGetSymbolAddress((void**)&p_xhi,  g_xhi4);
    cudaGetSymbolAddress((void**)&p_xlo,  g_xlo4);
    cudaGetSymbolAddress((void**)&p_mhi,  g_mhi4);
    cudaGetSymbolAddress((void**)&p_mlo,  g_mlo4);

    int smem_gemm = STAGES * STAGE_BYTES;
    cudaFuncSetAttribute(gemm_mma_kernel, cudaFuncAttributeMaxDynamicSharedMemorySize, smem_gemm);

    prep_kernel<<<M_QKV, CC>>>(Wq, bq, Wkv, bkv, Wproj, scale_param);

    int n4 = BB * CC * NN / 4;
    split_kernel<<<(n4 + 255) / 256, 256>>>((const float4*)x,
                                            (__nv_bfloat16*)p_xhi, (__nv_bfloat16*)p_xlo, n4);

    // QKV projection: 768x256 @ 256x4096 per batch
    gemm_mma_kernel<<<dim3(NN / 128, M_QKV / 128, BB), 256, smem_gemm>>>(
        (const __nv_bfloat16*)p_whi, (const __nv_bfloat16*)p_wlo,
        (const __nv_bfloat16*)p_xhi, (const __nv_bfloat16*)p_xlo,
        p_bcat, p_qkv, M_QKV);

    focus_kernel<<<dim3(NN / 256, BB), 256>>>();

    kvstate_kernel<<<dim3(BB * NH, SEGS), 256>>>();

    dwconv_kernel<<<dim3(16, BB * NH), 256>>>(dwc_w, dwc_b);

    attn_out_kernel<<<dim3(NN / 256, BB * NH), 256>>>();

    // Output projection: 256x256 @ 256x4096 per batch -> d_out
    gemm_mma_kernel<<<dim3(NN / 128, CC / 128, BB), 256, smem_gemm>>>(
        (const __nv_bfloat16*)p_pwhi, (const __nv_bfloat16*)p_pwlo,
        (const __nv_bfloat16*)p_mhi, (const __nv_bfloat16*)p_mlo,
        bproj, out, CC);
}